// round 8
// baseline (speedup 1.0000x reference)
#include <cuda_runtime.h>
#include <cuda_fp16.h>
#include <cuda_bf16.h>
#include <cstdint>

// ===========================================================================
// SLAYER SNN forward. GEMM1: mma.sync.m16n8k16 fp16, 2-part fp16 split of W1.
// hi part -> fp32 accumulator; mid part -> fp16 accumulator (|sum| ~1e-3,
// error ~3e-6, below decision noise). 4-stage cp.async pipeline (SW64).
// Spikegen: 8 threefry pairs/thread, vectorized loads+stores.
// ===========================================================================

#define BATCH 32
#define TBINS 300
#define FIN   3072
#define HID   410
#define NOUT  10
#define MROWS (BATCH * TBINS)          // 9600
#define NTOT  (MROWS * FIN)
#define HALFN (NTOT / 2)               // 14745600 = 4800 * 3072
#define NPAD  448

#define DECAY 0.90483743f
#define THETA 10.0f

// GEMM1 tiling
#define NPARTS 2
#define BM 256
#define BN 64
#define BK 32
#define KCH (FIN / BK)                 // 96
#define BROWS (NPARTS * BN)            // 128
#define A_ST_BYTES (BM * 64)           // 16384
#define B_ST_BYTES (BROWS * 64)        // 8192
#define STAGE_BYTES (A_ST_BYTES + B_ST_BYTES)   // 24576
#define NSTAGES 4
#define DSMEM_BYTES (NSTAGES * STAGE_BYTES)     // 98304
#define NCHUNK (STAGE_BYTES / 16)      // 1536
#define ACHUNK (A_ST_BYTES / 16)       // 1024

#define SWZ64(off) ((off) ^ (((off) >> 3) & 0x30))

// Scratch
__device__ __align__(16) __half        g_spikes[NTOT];
__device__ __align__(16) __half        g_W1s[NPARTS * NPAD * FIN];
__device__ __align__(16) float         g_a1[MROWS * HID];
__device__ __align__(16) __nv_bfloat16 g_s1[MROWS * HID];
__device__ __align__(16) float         g_a2[MROWS * NOUT];

// ---------------------------------------------------------------------------
__device__ __forceinline__ uint32_t smem_u32(const void* p) {
    uint32_t a;
    asm("{ .reg .u64 t; cvta.to.shared.u64 t, %1; cvt.u32.u64 %0, t; }" : "=r"(a) : "l"(p));
    return a;
}
__device__ __forceinline__ void cp16(uint32_t sa, const void* g) {
    asm volatile("cp.async.cg.shared.global [%0], [%1], 16;" :: "r"(sa), "l"(g));
}
__device__ __forceinline__ void ldsm4(uint32_t* r, uint32_t addr) {
    asm volatile("ldmatrix.sync.aligned.m8n8.x4.shared.b16 {%0,%1,%2,%3}, [%4];"
                 : "=r"(r[0]), "=r"(r[1]), "=r"(r[2]), "=r"(r[3]) : "r"(addr));
}
// fp32-accumulator mma (hi part)
__device__ __forceinline__ void mma16816f(float* c, const uint32_t* a,
                                          uint32_t b0, uint32_t b1) {
    asm volatile(
        "mma.sync.aligned.m16n8k16.row.col.f32.f16.f16.f32 "
        "{%0,%1,%2,%3}, {%4,%5,%6,%7}, {%8,%9}, {%0,%1,%2,%3};"
        : "+f"(c[0]), "+f"(c[1]), "+f"(c[2]), "+f"(c[3])
        : "r"(a[0]), "r"(a[1]), "r"(a[2]), "r"(a[3]), "r"(b0), "r"(b1));
}
// fp16-accumulator mma (mid part): c = 2 regs of f16x2
__device__ __forceinline__ void mma16816h(uint32_t* c, const uint32_t* a,
                                          uint32_t b0, uint32_t b1) {
    asm volatile(
        "mma.sync.aligned.m16n8k16.row.col.f16.f16.f16.f16 "
        "{%0,%1}, {%2,%3,%4,%5}, {%6,%7}, {%0,%1};"
        : "+r"(c[0]), "+r"(c[1])
        : "r"(a[0]), "r"(a[1]), "r"(a[2]), "r"(a[3]), "r"(b0), "r"(b1));
}

// ---------------------------------------------------------------------------
// Kernel 1: threefry spike generation, 8 pairs/thread, vectorized.
// Pair (i, i+HALFN): same column f, batch b and b+16. Also W1 2-part split
// on the first HID*FIN/8 threads (8 elems each).
// ---------------------------------------------------------------------------
__device__ __forceinline__ uint32_t rotl32(uint32_t x, int r) {
    return (x << r) | (x >> (32 - r));
}

__global__ void __launch_bounds__(256) spikegen_kernel(const float* __restrict__ inp,
                                                       const float* __restrict__ W1) {
    const uint32_t t = blockIdx.x * 256u + threadIdx.x;

    // --- W1 split, 8 consecutive elements per thread ---
    if (t < (HID * FIN) / 8) {
        int base = t * 8;
        int n = base / FIN, k = base % FIN;
        float4 wa = *(const float4*)&W1[base];
        float4 wb = *(const float4*)&W1[base + 4];
        float w[8] = {wa.x, wa.y, wa.z, wa.w, wb.x, wb.y, wb.z, wb.w};
        uint32_t hh[4], mm[4];
#pragma unroll
        for (int q = 0; q < 4; q++) {
            __half h0 = __float2half_rn(w[2 * q]);
            __half h1 = __float2half_rn(w[2 * q + 1]);
            __half m0 = __float2half_rn(w[2 * q] - __half2float(h0));
            __half m1 = __float2half_rn(w[2 * q + 1] - __half2float(h1));
            hh[q] = (uint32_t)__half_as_ushort(h0) | ((uint32_t)__half_as_ushort(h1) << 16);
            mm[q] = (uint32_t)__half_as_ushort(m0) | ((uint32_t)__half_as_ushort(m1) << 16);
        }
        *(uint4*)&g_W1s[(0 * NPAD + n) * FIN + k] = make_uint4(hh[0], hh[1], hh[2], hh[3]);
        *(uint4*)&g_W1s[(1 * NPAD + n) * FIN + k] = make_uint4(mm[0], mm[1], mm[2], mm[3]);
    }

    const uint32_t i0 = t * 8;
    if (i0 >= HALFN) return;

    const uint32_t ba = i0 / (TBINS * FIN);
    const uint32_t fa = i0 % FIN;                 // 8-aligned; same f for both halves
    float4 p0 = *(const float4*)&inp[ba * FIN + fa];
    float4 p1 = *(const float4*)&inp[ba * FIN + fa + 4];
    float4 q0 = *(const float4*)&inp[(ba + 16) * FIN + fa];
    float4 q1 = *(const float4*)&inp[(ba + 16) * FIN + fa + 4];
    float pa[8] = {p0.x, p0.y, p0.z, p0.w, p1.x, p1.y, p1.z, p1.w};
    float pb[8] = {q0.x, q0.y, q0.z, q0.w, q1.x, q1.y, q1.z, q1.w};

    const uint32_t k0 = 0u, k1 = 42u, k2 = 0x1BD11BDAu ^ k0 ^ k1;
    unsigned short sa[8], sb[8];

#pragma unroll
    for (int j = 0; j < 8; j++) {
        uint32_t i = i0 + j;
        uint32_t x0 = i + k0;
        uint32_t x1 = (i + HALFN) + k1;
#define TF_RND(r) { x0 += x1; x1 = rotl32(x1, (r)) ^ x0; }
        TF_RND(13) TF_RND(15) TF_RND(26) TF_RND(6)
        x0 += k1; x1 += k2 + 1u;
        TF_RND(17) TF_RND(29) TF_RND(16) TF_RND(24)
        x0 += k2; x1 += k0 + 2u;
        TF_RND(13) TF_RND(15) TF_RND(26) TF_RND(6)
        x0 += k0; x1 += k1 + 3u;
        TF_RND(17) TF_RND(29) TF_RND(16) TF_RND(24)
        x0 += k1; x1 += k2 + 4u;
        TF_RND(13) TF_RND(15) TF_RND(26) TF_RND(6)
        x0 += k2; x1 += k0 + 5u;
#undef TF_RND
        float u0 = __uint_as_float((x0 >> 9) | 0x3F800000u) - 1.0f;
        float u1 = __uint_as_float((x1 >> 9) | 0x3F800000u) - 1.0f;
        sa[j] = (u0 < pa[j]) ? (unsigned short)0x3C00 : (unsigned short)0;
        sb[j] = (u1 < pb[j]) ? (unsigned short)0x3C00 : (unsigned short)0;
    }

    uint32_t oa[4], ob[4];
#pragma unroll
    for (int q = 0; q < 4; q++) {
        oa[q] = (uint32_t)sa[2 * q] | ((uint32_t)sa[2 * q + 1] << 16);
        ob[q] = (uint32_t)sb[2 * q] | ((uint32_t)sb[2 * q + 1] << 16);
    }
    *(uint4*)&g_spikes[i0]         = make_uint4(oa[0], oa[1], oa[2], oa[3]);
    *(uint4*)&g_spikes[i0 + HALFN] = make_uint4(ob[0], ob[1], ob[2], ob[3]);
}

// ---------------------------------------------------------------------------
// Kernel 2: GEMM1, 4-stage cp.async pipeline, SW64 smem.
// ---------------------------------------------------------------------------
__device__ __forceinline__ void load_stage(uint32_t sbase, int m0, int n0, int k0,
                                           int tid) {
    uint32_t stB = sbase + A_ST_BYTES;
#pragma unroll
    for (int c = tid; c < NCHUNK; c += 256) {
        uint32_t sa;
        const __half* g;
        if (c < ACHUNK) {
            int row = c >> 2, q = c & 3;
            int m = m0 + row;
            if (m >= MROWS) m = MROWS - 1;
            sa = sbase + SWZ64(row * 64 + q * 16);
            g = &g_spikes[(size_t)m * FIN + k0 + q * 8];
        } else {
            int cc = c - ACHUNK;
            int br = cc >> 2, q = cc & 3;
            int part = br >> 6, nr = br & 63;
            sa = stB + SWZ64(br * 64 + q * 16);
            g = &g_W1s[((size_t)part * NPAD + n0 + nr) * FIN + k0 + q * 8];
        }
        cp16(sa, g);
    }
    asm volatile("cp.async.commit_group;" ::: "memory");
}

__global__ void __launch_bounds__(256, 2) gemm1_mma_kernel() {
    extern __shared__ char dsmem[];
    const int tid = threadIdx.x;
    const int lane = tid & 31, wid = tid >> 5;
    const int wm = wid & 3;
    const int wn = wid >> 2;
    const int m0 = blockIdx.x * BM;
    const int n0 = blockIdx.y * BN;

    const uint32_t sbase = smem_u32(dsmem);

    float    acch[4][4][4];           // hi part, fp32 acc
    uint32_t accm[4][4][2];           // mid part, fp16x2 acc
#pragma unroll
    for (int i = 0; i < 4; i++)
#pragma unroll
        for (int j = 0; j < 4; j++) {
#pragma unroll
            for (int c = 0; c < 4; c++) acch[i][j][c] = 0.0f;
            accm[i][j][0] = 0u; accm[i][j][1] = 0u;
        }

    const int ltr = (lane & 7) + ((lane >> 3) & 1) * 8;
    const int lkb = (lane >> 4) * 16;

    load_stage(sbase + 0 * STAGE_BYTES, m0, n0, 0 * BK, tid);
    load_stage(sbase + 1 * STAGE_BYTES, m0, n0, 1 * BK, tid);
    load_stage(sbase + 2 * STAGE_BYTES, m0, n0, 2 * BK, tid);

    for (int kc = 0; kc < KCH; kc++) {
        const int rem = KCH - 1 - kc;
        if (rem >= 2)      asm volatile("cp.async.wait_group 2;" ::: "memory");
        else if (rem == 1) asm volatile("cp.async.wait_group 1;" ::: "memory");
        else               asm volatile("cp.async.wait_group 0;" ::: "memory");
        __syncthreads();

        if (kc + 3 < KCH)
            load_stage(sbase + ((kc + 3) & 3) * STAGE_BYTES, m0, n0, (kc + 3) * BK, tid);

        const uint32_t sA = sbase + (kc & 3) * STAGE_BYTES;
        const uint32_t sB = sA + A_ST_BYTES;

#pragma unroll
        for (int kt = 0; kt < 2; kt++) {
            const int kb = kt * 32 + lkb;
            uint32_t aF[4][4];
#pragma unroll
            for (int im = 0; im < 4; im++) {
                int row = wm * 64 + im * 16 + ltr;
                ldsm4(aF[im], sA + SWZ64(row * 64 + kb));
            }
            // hi part (rows 0..63 of B block), fp32 acc
            {
                uint32_t bF[2][4];
#pragma unroll
                for (int j = 0; j < 2; j++) {
                    int row = wn * 32 + j * 16 + ltr;
                    ldsm4(bF[j], sB + SWZ64(row * 64 + kb));
                }
#pragma unroll
                for (int im = 0; im < 4; im++)
#pragma unroll
                    for (int j = 0; j < 2; j++) {
                        mma16816f(acch[im][j * 2 + 0], aF[im], bF[j][0], bF[j][2]);
                        mma16816f(acch[im][j * 2 + 1], aF[im], bF[j][1], bF[j][3]);
                    }
            }
            // mid part (rows 64..127 of B block), fp16 acc
            {
                uint32_t bF[2][4];
#pragma unroll
                for (int j = 0; j < 2; j++) {
                    int row = 64 + wn * 32 + j * 16 + ltr;
                    ldsm4(bF[j], sB + SWZ64(row * 64 + kb));
                }
#pragma unroll
                for (int im = 0; im < 4; im++)
#pragma unroll
                    for (int j = 0; j < 2; j++) {
                        mma16816h(accm[im][j * 2 + 0], aF[im], bF[j][0], bF[j][2]);
                        mma16816h(accm[im][j * 2 + 1], aF[im], bF[j][1], bF[j][3]);
                    }
            }
        }
    }

    // epilogue: out = hi + mid
#pragma unroll
    for (int im = 0; im < 4; im++) {
        int m = m0 + wm * 64 + im * 16 + (lane >> 2);
#pragma unroll
        for (int jn = 0; jn < 4; jn++) {
            int n = n0 + wn * 32 + jn * 8 + (lane & 3) * 2;
            if (n < HID) {
                float2 lo = __half22float2(*(__half2*)&accm[im][jn][0]); // rows m, cols n,n+1
                float2 hi = __half22float2(*(__half2*)&accm[im][jn][1]); // rows m+8
                if (m < MROWS)
                    *(float2*)&g_a1[(size_t)m * HID + n] =
                        make_float2(acch[im][jn][0] + lo.x, acch[im][jn][1] + lo.y);
                if (m + 8 < MROWS)
                    *(float2*)&g_a1[(size_t)(m + 8) * HID + n] =
                        make_float2(acch[im][jn][2] + hi.x, acch[im][jn][3] + hi.y);
            }
        }
    }
}

// ---------------------------------------------------------------------------
// Kernel 3: PSP + threshold layer 1 -> bf16. Batch-10 prefetch.
// ---------------------------------------------------------------------------
__global__ void __launch_bounds__(256) psp1_kernel() {
    int tid = blockIdx.x * blockDim.x + threadIdx.x;
    if (tid >= BATCH * HID) return;
    int b = tid / HID;
    int o = tid % HID;
    const float* src = &g_a1[(size_t)b * TBINS * HID + o];
    __nv_bfloat16* dst = &g_s1[(size_t)b * TBINS * HID + o];
    float u = 0.0f;
    for (int tb = 0; tb < TBINS; tb += 10) {
        float x[10];
#pragma unroll
        for (int q = 0; q < 10; q++) x[q] = src[(tb + q) * HID];
#pragma unroll
        for (int q = 0; q < 10; q++) {
            u = fmaf(DECAY, u, x[q]);
            dst[(tb + q) * HID] = __float2bfloat16((u >= THETA) ? 1.0f : 0.0f);
        }
    }
}

// ---------------------------------------------------------------------------
// Kernel 4: GEMM2 (one warp per row, bf16x2 vectorized)
// ---------------------------------------------------------------------------
__global__ void __launch_bounds__(256) gemm2_kernel(const float* __restrict__ W2) {
    __shared__ float2 W2s[NOUT][(HID + 1) / 2 + 1];
    for (int idx = threadIdx.x; idx < NOUT * 206; idx += 256) {
        int j = idx / 206, kp = idx % 206;
        float w0 = (kp * 2 < HID) ? W2[j * HID + kp * 2] : 0.0f;
        float w1 = (kp * 2 + 1 < HID) ? W2[j * HID + kp * 2 + 1] : 0.0f;
        W2s[j][kp] = make_float2(w0, w1);
    }
    __syncthreads();

    int warp = threadIdx.x >> 5;
    int lane = threadIdx.x & 31;
    int m = blockIdx.x * 8 + warp;

    float p[NOUT];
#pragma unroll
    for (int j = 0; j < NOUT; j++) p[j] = 0.0f;

    for (int kp = lane; kp < 205; kp += 32) {
        __nv_bfloat162 sv = *(const __nv_bfloat162*)&g_s1[m * HID + kp * 2];
        float s0 = __bfloat162float(sv.x);
        float s1v = __bfloat162float(sv.y);
#pragma unroll
        for (int j = 0; j < NOUT; j++) {
            float2 w = W2s[j][kp];
            p[j] = fmaf(s0, w.x, fmaf(s1v, w.y, p[j]));
        }
    }

#pragma unroll
    for (int j = 0; j < NOUT; j++)
#pragma unroll
        for (int off = 16; off > 0; off >>= 1)
            p[j] += __shfl_down_sync(0xffffffffu, p[j], off);

    if (lane == 0) {
#pragma unroll
        for (int j = 0; j < NOUT; j++)
            g_a2[m * NOUT + j] = p[j];
    }
}

// ---------------------------------------------------------------------------
// Kernel 5: PSP + threshold layer 2 -> out[b, j, t]. Batch-10 prefetch.
// ---------------------------------------------------------------------------
__global__ void psp2_kernel(float* __restrict__ out) {
    int tid = blockIdx.x * blockDim.x + threadIdx.x;
    if (tid >= BATCH * NOUT) return;
    int b = tid / NOUT;
    int j = tid % NOUT;
    const float* src = &g_a2[(size_t)b * TBINS * NOUT + j];
    float* dst = &out[((size_t)b * NOUT + j) * TBINS];
    float u = 0.0f;
    for (int tb = 0; tb < TBINS; tb += 10) {
        float x[10];
#pragma unroll
        for (int q = 0; q < 10; q++) x[q] = src[(tb + q) * NOUT];
#pragma unroll
        for (int q = 0; q < 10; q++) {
            u = fmaf(DECAY, u, x[q]);
            dst[tb + q] = (u >= THETA) ? 1.0f : 0.0f;
        }
    }
}

// ---------------------------------------------------------------------------
extern "C" void kernel_launch(void* const* d_in, const int* in_sizes, int n_in,
                              void* d_out, int out_size) {
    const float* inp = (const float*)d_in[0];   // [32,3,32,32]
    const float* W1  = (const float*)d_in[1];   // [410,3072]
    const float* W2  = (const float*)d_in[2];   // [10,410]
    float* out = (float*)d_out;                 // [32,10,300]

    cudaFuncSetAttribute(gemm1_mma_kernel,
                         cudaFuncAttributeMaxDynamicSharedMemorySize, DSMEM_BYTES);

    spikegen_kernel<<<HALFN / 8 / 256, 256>>>(inp, W1);   // 7200 blocks

    dim3 g1((MROWS + BM - 1) / BM, NPAD / BN);   // (38, 7)
    gemm1_mma_kernel<<<g1, 256, DSMEM_BYTES>>>();

    psp1_kernel<<<(BATCH * HID + 255) / 256, 256>>>();
    gemm2_kernel<<<MROWS / 8, 256>>>(W2);
    psp2_kernel<<<2, 160>>>(out);
}